// round 10
// baseline (speedup 1.0000x reference)
#include <cuda_runtime.h>
#include <math.h>

#define HID     2048
#define KVD     512
#define HEADS   16
#define GROUPS  4
#define HDIM    128
#define BATCH   2
#define SEQ     2048
#define MROWS   (BATCH*SEQ)   // 4096

// ---------------- scratch (no cudaMalloc allowed) ----------------
__device__ float g_Q[(size_t)MROWS * HID];    // tf32, hdim cols pair-permuted
__device__ float g_K[(size_t)MROWS * KVD];    // tf32, hdim cols pair-permuted
__device__ float g_V[(size_t)MROWS * KVD];    // tf32, key rows pair-interleaved
__device__ float g_O[(size_t)MROWS * HID];    // tf32, k-dim pair-permuted (GEMM A layout)
__device__ float g_Xt[(size_t)MROWS * HID];   // tf32 copy of X, k-dim pair-permuted
__device__ float g_Wqt[(size_t)HID * HID];    // W^T, k-dim pair-permuted
__device__ float g_Wkt[(size_t)HID * KVD];
__device__ float g_Wvt[(size_t)HID * KVD];
__device__ float g_Wot[(size_t)HID * HID];

// ---------------- helpers ----------------
__device__ __forceinline__ unsigned f2tf(float x) {
    unsigned u;
    asm("cvt.rna.tf32.f32 %0, %1;" : "=r"(u) : "f"(x));
    return u;
}
__device__ __forceinline__ float tfs(float x) { return __uint_as_float(f2tf(x)); }
__device__ __forceinline__ unsigned uf(float x) { return __float_as_uint(x); }

// pair permutation within an 8-group: orig j -> stored position (j,j+4 adjacent)
__host__ __device__ __forceinline__ int pcol(int j) { return (j < 4) ? 2 * j : 2 * (j - 4) + 1; }

__device__ __forceinline__ void mma_tf32(float c[4], const unsigned a[4], const unsigned b[2]) {
    asm volatile(
        "mma.sync.aligned.m16n8k8.row.col.f32.tf32.tf32.f32 "
        "{%0,%1,%2,%3},{%4,%5,%6,%7},{%8,%9},{%0,%1,%2,%3};\n"
        : "+f"(c[0]), "+f"(c[1]), "+f"(c[2]), "+f"(c[3])
        : "r"(a[0]), "r"(a[1]), "r"(a[2]), "r"(a[3]), "r"(b[0]), "r"(b[1]));
}

__device__ __forceinline__ void cp_async16(void* smem, const void* gmem) {
    unsigned sa = (unsigned)__cvta_generic_to_shared(smem);
    asm volatile("cp.async.cg.shared.global [%0], [%1], 16;\n" :: "r"(sa), "l"(gmem));
}
#define CP_COMMIT asm volatile("cp.async.commit_group;\n")
#define CP_WAIT0  asm volatile("cp.async.wait_group 0;\n")

// ============ tf32 pre-cast with k-pair permutation (A-side operands) ============
__global__ __launch_bounds__(256) void tf32_cast_perm(const float* __restrict__ in,
                                                      float* __restrict__ out, int n4)
{
    int i = blockIdx.x * 256 + threadIdx.x;
    if (i < n4) {
        float4 v = ((const float4*)in)[i];
        int f = i * 4;
        int base = f & ~7, j = f & 7;       // j in {0,4}
        out[base + pcol(j + 0)] = tfs(v.x);
        out[base + pcol(j + 1)] = tfs(v.y);
        out[base + pcol(j + 2)] = tfs(v.z);
        out[base + pcol(j + 3)] = tfs(v.w);
    }
}

// ============ weight transpose + tf32 + k-pair permutation (B-side operands) =====
// out[n][ (k&~7)+pcol(k&7) ] = tf32( in[k][n] )
__global__ __launch_bounds__(256) void wtrans(const float* __restrict__ in,
                                              float* __restrict__ out, int K, int N)
{
    __shared__ float t[32][33];
    const int k0 = blockIdx.x * 32, n0 = blockIdx.y * 32;
    const int tx = threadIdx.x & 31, ty = threadIdx.x >> 5;   // 32 x 8
#pragma unroll
    for (int u = 0; u < 4; u++) {
        int k = k0 + ty + u * 8;
        t[ty + u * 8][tx] = in[(size_t)k * N + n0 + tx];
    }
    __syncthreads();
    const int kc = (tx & ~7) + pcol(tx & 7);
#pragma unroll
    for (int u = 0; u < 4; u++) {
        int n = n0 + ty + u * 8;
        out[(size_t)n * K + k0 + kc] = tfs(t[tx][ty + u * 8]);
    }
}

// ================= GEMM (tf32 tensor cores): C[M,N] = A[M,K]@W[K,N] + bias ===========
// A: [M][K] k-pair-permuted.  B: W^T [N][K] k-pair-permuted (same permutation).
// All fragment gathers are conflict-free LDS.64 (pad 40: 20 = 4 mod 16).
// EPI: 0 = plain fp32 out; 1 = tf32 + N-col pair-permute (Q,K); 2 = tf32 + row interleave (V)
#define GBK 32
#define G_TS (128*40)
#define GSMEM (4*G_TS*4)   // 2 stages x (A+B) = 81920 B

template<int EPI>
__global__ __launch_bounds__(256, 2) void gemm_mma(
    const float* __restrict__ A, const float* __restrict__ Bt,
    const float* __restrict__ bias, float* __restrict__ C,
    int M, int N, int K)
{
    extern __shared__ float gsm[];
    float (*As)[128][40] = (float(*)[128][40])gsm;
    float (*Bs)[128][40] = (float(*)[128][40])(gsm + 2 * G_TS);

    const int tid = threadIdx.x;
    const int lane = tid & 31, wid = tid >> 5;
    const int gid = lane >> 2, tig = lane & 3;
    const int wm = wid >> 1, wn = wid & 1;
    const int bm = blockIdx.y * 128, bn = blockIdx.x * 128;

    float acc[2][8][4];
#pragma unroll
    for (int i = 0; i < 2; i++)
#pragma unroll
        for (int j = 0; j < 8; j++)
#pragma unroll
            for (int v = 0; v < 4; v++) acc[i][j][v] = 0.f;

    const int T = K / GBK;

    // loaders: A tile 128x32 and B tile 128x32, both K-major, 8 chunks/row
    auto load_stage = [&](int st, int t) {
        const int k0 = t * GBK;
#pragma unroll
        for (int u = 0; u < 4; u++) {
            int id = tid + u * 256;
            int r = id >> 3, c = id & 7;
            cp_async16(&As[st][r][c * 4], A  + (size_t)(bm + r) * K + k0 + c * 4);
            cp_async16(&Bs[st][r][c * 4], Bt + (size_t)(bn + r) * K + k0 + c * 4);
        }
    };

    load_stage(0, 0);
    CP_COMMIT;

    for (int t = 0; t < T; t++) {
        const int st = t & 1;
        CP_WAIT0;
        __syncthreads();
        if (t + 1 < T) {
            load_stage(st ^ 1, t + 1);
            CP_COMMIT;
        }

#pragma unroll
        for (int kk = 0; kk < GBK; kk += 8) {
            unsigned a[2][4];
#pragma unroll
            for (int mt = 0; mt < 2; mt++) {
                int r = wm * 32 + mt * 16 + gid;
                float2 a0 = *(const float2*)&As[st][r][kk + 2 * tig];
                float2 a1 = *(const float2*)&As[st][r + 8][kk + 2 * tig];
                a[mt][0] = uf(a0.x); a[mt][1] = uf(a1.x);
                a[mt][2] = uf(a0.y); a[mt][3] = uf(a1.y);
            }
#pragma unroll
            for (int nt = 0; nt < 8; nt++) {
                int c = wn * 64 + nt * 8 + gid;
                float2 bv = *(const float2*)&Bs[st][c][kk + 2 * tig];
                unsigned bf[2] = {uf(bv.x), uf(bv.y)};
                mma_tf32(acc[0][nt], a[0], bf);
                mma_tf32(acc[1][nt], a[1], bf);
            }
        }
    }

    // epilogue
    const int pj0 = pcol(2 * tig), pj1 = pcol(2 * tig + 1);
#pragma unroll
    for (int mt = 0; mt < 2; mt++) {
        int rbase = bm + wm * 32 + mt * 16 + gid;
#pragma unroll
        for (int nt = 0; nt < 8; nt++) {
            int cb = bn + wn * 64 + nt * 8;
            int c = cb + 2 * tig;
            float bx = bias[c], by = bias[c + 1];
            float v0 = acc[mt][nt][0] + bx, v1 = acc[mt][nt][1] + by;
            float v2 = acc[mt][nt][2] + bx, v3 = acc[mt][nt][3] + by;
            if (EPI == 0) {
                *(float2*)&C[(size_t)rbase * N + c] = make_float2(v0, v1);
                *(float2*)&C[(size_t)(rbase + 8) * N + c] = make_float2(v2, v3);
            } else if (EPI == 1) {
                C[(size_t)rbase * N + cb + pj0] = tfs(v0);
                C[(size_t)rbase * N + cb + pj1] = tfs(v1);
                C[(size_t)(rbase + 8) * N + cb + pj0] = tfs(v2);
                C[(size_t)(rbase + 8) * N + cb + pj1] = tfs(v3);
            } else {
                // V: row pair-interleave addr(r,c) = (r&~7)*N + (r&3)*2N + c*2 + ((r>>2)&1)
#pragma unroll
                for (int rr = 0; rr < 2; rr++) {
                    int r = rbase + rr * 8;
                    size_t base = (size_t)(r & ~7) * N + (size_t)(r & 3) * 2 * N + ((r >> 2) & 1);
                    float a0 = rr ? v2 : v0, a1 = rr ? v3 : v1;
                    C[base + (size_t)c * 2] = tfs(a0);
                    C[base + (size_t)(c + 1) * 2] = tfs(a1);
                }
            }
        }
    }
}

// ================= Flash attention on tensor cores =================
// 128 threads = 4 warps (warp owns 16 Q rows), Q tile 64x128, K/V tiles 32x128,
// double-buffered cp.async, 2 CTAs/SM. Conflict-free LDS.64 gathers everywhere.
#define AQP 136
#define AKP 136
#define AVL 264
#define APP 40
#define OQ_  0
#define OKs  (64*AQP)                  // 8704
#define OVs  (OKs + 2*32*AKP)          // +8704
#define OPs  (OVs + 2*16*AVL)          // +8448
#define OMs  (OPs + 64*APP)            // +2560
#define ASMEM ((OMs + 2*32) * 4)       // 113920 B -> 2 CTAs/SM

__global__ __launch_bounds__(128, 2) void attn_mma(const int* __restrict__ mask)
{
    extern __shared__ float sm[];
    float (*Qs)[AQP]     = (float(*)[AQP])(sm + OQ_);
    float (*Ks)[32][AKP] = (float(*)[32][AKP])(sm + OKs);
    float (*Vs)[16][AVL] = (float(*)[16][AVL])(sm + OVs);
    float (*Ps)[APP]     = (float(*)[APP])(sm + OPs);
    int (*Ms)[32]        = (int(*)[32])(sm + OMs);

    const int tid = threadIdx.x;
    const int w = tid >> 5, lane = tid & 31;
    const int gid = lane >> 2, tig = lane & 3;
    const int qt = blockIdx.x, h = blockIdx.y, b = blockIdx.z;
    const int g = h % GROUPS;
    const int q0 = qt * 64;

    const float scale = 0.08838834764831845f;  // 1/sqrt(128)
    const float* Qg = g_Q + (size_t)(b * SEQ + q0) * HID + h * HDIM;
    const float* Kg0 = g_K + (size_t)(b * SEQ) * KVD + g * HDIM;
    const float* Vg0 = g_V + (size_t)(b * SEQ) * KVD;
    const int*   Mg0 = mask + b * SEQ;

    auto issue_kv = [&](int st, int kt) {
        const int k0 = kt * 32;
#pragma unroll
        for (int u = 0; u < 8; u++) {
            int id = tid + u * 128;
            int r = id >> 5, c4 = id & 31;
            cp_async16(&Ks[st][r][c4 * 4], Kg0 + (size_t)(k0 + r) * KVD + c4 * 4);
            int line = id >> 6, cc = id & 63;
            const float* src = Vg0 + (size_t)(k0 + (line >> 2) * 8) * KVD
                             + (size_t)(line & 3) * 2 * KVD + g * HDIM * 2 + cc * 4;
            cp_async16(&Vs[st][line][cc * 4], src);
        }
        if (tid < 8) cp_async16(&Ms[st][tid * 4], Mg0 + k0 + tid * 4);
    };

    issue_kv(0, 0);
    CP_COMMIT;

    // Q prologue: straight copy (already col-permuted + tf32), scale + re-round
#pragma unroll
    for (int u = 0; u < 16; u++) {
        int idx = tid + u * 128;
        int r = idx >> 5, c4 = idx & 31;
        float4 v = *(const float4*)(Qg + (size_t)r * HID + c4 * 4);
        float4 o = make_float4(tfs(v.x * scale), tfs(v.y * scale),
                               tfs(v.z * scale), tfs(v.w * scale));
        *(float4*)&Qs[r][c4 * 4] = o;
    }

    float m_run[2] = {-1e30f, -1e30f};
    float l_run[2] = {0.f, 0.f};
    float o_acc[16][4];
#pragma unroll
    for (int nt = 0; nt < 16; nt++)
#pragma unroll
        for (int v = 0; v < 4; v++) o_acc[nt][v] = 0.f;

    const int r = w * 16 + gid;
    const int pj0 = pcol(2 * tig), pj1 = pcol(2 * tig + 1);

    for (int kt = 0; kt < SEQ / 32; kt++) {
        const int st = kt & 1;
        CP_WAIT0;
        __syncthreads();
        if (kt + 1 < SEQ / 32) {
            issue_kv(st ^ 1, kt + 1);
            CP_COMMIT;
        }

        // ---- S = Q @ K^T ----
        float s[4][4];
#pragma unroll
        for (int nt = 0; nt < 4; nt++)
#pragma unroll
            for (int v = 0; v < 4; v++) s[nt][v] = 0.f;

#pragma unroll
        for (int ks = 0; ks < 16; ks++) {
            const int kk = ks * 8;
            float2 q0 = *(const float2*)&Qs[r][kk + 2 * tig];
            float2 q1 = *(const float2*)&Qs[r + 8][kk + 2 * tig];
            unsigned qa[4] = {uf(q0.x), uf(q1.x), uf(q0.y), uf(q1.y)};
#pragma unroll
            for (int nt = 0; nt < 4; nt++) {
                float2 kv = *(const float2*)&Ks[st][nt * 8 + gid][kk + 2 * tig];
                unsigned kb[2] = {uf(kv.x), uf(kv.y)};
                mma_tf32(s[nt], qa, kb);
            }
        }

        // ---- mask ----
#pragma unroll
        for (int nt = 0; nt < 4; nt++) {
            int c = nt * 8 + 2 * tig;
            if (Ms[st][c] == 0)     { s[nt][0] = -1e30f; s[nt][2] = -1e30f; }
            if (Ms[st][c + 1] == 0) { s[nt][1] = -1e30f; s[nt][3] = -1e30f; }
        }

        // ---- online softmax ----
#pragma unroll
        for (int hh = 0; hh < 2; hh++) {
            float mx = -1e30f;
#pragma unroll
            for (int nt = 0; nt < 4; nt++)
                mx = fmaxf(mx, fmaxf(s[nt][2 * hh], s[nt][2 * hh + 1]));
            mx = fmaxf(mx, __shfl_xor_sync(0xffffffffu, mx, 1));
            mx = fmaxf(mx, __shfl_xor_sync(0xffffffffu, mx, 2));
            float mnew = fmaxf(m_run[hh], mx);
            float corr = __expf(m_run[hh] - mnew);
            float sum = 0.f;
#pragma unroll
            for (int nt = 0; nt < 4; nt++) {
                float p0 = __expf(s[nt][2 * hh] - mnew);
                float p1 = __expf(s[nt][2 * hh + 1] - mnew);
                s[nt][2 * hh] = p0; s[nt][2 * hh + 1] = p1;
                sum += p0 + p1;
            }
            sum += __shfl_xor_sync(0xffffffffu, sum, 1);
            sum += __shfl_xor_sync(0xffffffffu, sum, 2);
            l_run[hh] = l_run[hh] * corr + sum;
            if (mnew > m_run[hh]) {
                m_run[hh] = mnew;
#pragma unroll
                for (int nt = 0; nt < 16; nt++) {
                    o_acc[nt][2 * hh] *= corr;
                    o_acc[nt][2 * hh + 1] *= corr;
                }
            }
        }

        // ---- store P (key-col pair permuted, matches V interleave) ----
#pragma unroll
        for (int nt = 0; nt < 4; nt++) {
            int cb = nt * 8;
            Ps[r][cb + pj0] = tfs(s[nt][0]);
            Ps[r][cb + pj1] = tfs(s[nt][1]);
            Ps[r + 8][cb + pj0] = tfs(s[nt][2]);
            Ps[r + 8][cb + pj1] = tfs(s[nt][3]);
        }
        __syncwarp();

        // ---- O += P @ V ----
#pragma unroll
        for (int ks = 0; ks < 4; ks++) {
            const int kk = ks * 8;
            float2 p0 = *(const float2*)&Ps[r][kk + 2 * tig];
            float2 p1 = *(const float2*)&Ps[r + 8][kk + 2 * tig];
            unsigned pa[4] = {uf(p0.x), uf(p1.x), uf(p0.y), uf(p1.y)};
            const int kp = kk / 2 + tig;
#pragma unroll
            for (int nt = 0; nt < 16; nt++) {
                float2 vv = *(const float2*)&Vs[st][kp][(nt * 8 + gid) * 2];
                unsigned vb[2] = {uf(vv.x), uf(vv.y)};
                mma_tf32(o_acc[nt], pa, vb);
            }
        }
    }

    // ---- epilogue: O /= l, tf32-rounded, k-pair-permuted for the out-proj GEMM ----
    float* Og = g_O + (size_t)(b * SEQ + q0) * HID + h * HDIM;
    const float i0 = 1.f / l_run[0], i1 = 1.f / l_run[1];
#pragma unroll
    for (int nt = 0; nt < 16; nt++) {
        int cb = nt * 8;
        Og[(size_t)r * HID + cb + pj0] = tfs(o_acc[nt][0] * i0);
        Og[(size_t)r * HID + cb + pj1] = tfs(o_acc[nt][1] * i0);
        Og[(size_t)(r + 8) * HID + cb + pj0] = tfs(o_acc[nt][2] * i1);
        Og[(size_t)(r + 8) * HID + cb + pj1] = tfs(o_acc[nt][3] * i1);
    }
}

// ================= launch =================
extern "C" void kernel_launch(void* const* d_in, const int* in_sizes, int n_in,
                              void* d_out, int out_size)
{
    const float* X    = (const float*)d_in[0];
    const int*   mask = (const int*)  d_in[1];
    const float* Wq   = (const float*)d_in[2];
    const float* bq   = (const float*)d_in[3];
    const float* Wk   = (const float*)d_in[4];
    const float* bk   = (const float*)d_in[5];
    const float* Wv   = (const float*)d_in[6];
    const float* bv   = (const float*)d_in[7];
    const float* Wo   = (const float*)d_in[8];
    const float* bo   = (const float*)d_in[9];
    float* out = (float*)d_out;

    float *Qp, *Kp, *Vp, *Op, *Xt, *Wqt, *Wkt, *Wvt, *Wot;
    cudaGetSymbolAddress((void**)&Qp, g_Q);
    cudaGetSymbolAddress((void**)&Kp, g_K);
    cudaGetSymbolAddress((void**)&Vp, g_V);
    cudaGetSymbolAddress((void**)&Op, g_O);
    cudaGetSymbolAddress((void**)&Xt, g_Xt);
    cudaGetSymbolAddress((void**)&Wqt, g_Wqt);
    cudaGetSymbolAddress((void**)&Wkt, g_Wkt);
    cudaGetSymbolAddress((void**)&Wvt, g_Wvt);
    cudaGetSymbolAddress((void**)&Wot, g_Wot);

    cudaFuncSetAttribute(gemm_mma<0>, cudaFuncAttributeMaxDynamicSharedMemorySize, GSMEM);
    cudaFuncSetAttribute(gemm_mma<1>, cudaFuncAttributeMaxDynamicSharedMemorySize, GSMEM);
    cudaFuncSetAttribute(gemm_mma<2>, cudaFuncAttributeMaxDynamicSharedMemorySize, GSMEM);
    cudaFuncSetAttribute(attn_mma, cudaFuncAttributeMaxDynamicSharedMemorySize, ASMEM);

    // pre-round + permute A-side; transpose + pre-round + permute B-side
    {
        int nX = MROWS * HID / 4;
        tf32_cast_perm<<<(nX + 255) / 256, 256>>>(X, Xt, nX);
        wtrans<<<dim3(HID / 32, HID / 32), 256>>>(Wq, Wqt, HID, HID);
        wtrans<<<dim3(HID / 32, KVD / 32), 256>>>(Wk, Wkt, HID, KVD);
        wtrans<<<dim3(HID / 32, KVD / 32), 256>>>(Wv, Wvt, HID, KVD);
        wtrans<<<dim3(HID / 32, HID / 32), 256>>>(Wo, Wot, HID, HID);
    }

    dim3 blk(256);
    gemm_mma<1><<<dim3(HID / 128, MROWS / 128), blk, GSMEM>>>(Xt, Wqt, bq, Qp, MROWS, HID, HID);
    gemm_mma<1><<<dim3(KVD / 128, MROWS / 128), blk, GSMEM>>>(Xt, Wkt, bk, Kp, MROWS, KVD, HID);
    gemm_mma<2><<<dim3(KVD / 128, MROWS / 128), blk, GSMEM>>>(Xt, Wvt, bv, Vp, MROWS, KVD, HID);

    attn_mma<<<dim3(SEQ / 64, HEADS, BATCH), dim3(128), ASMEM>>>(mask);

    gemm_mma<0><<<dim3(HID / 128, MROWS / 128), blk, GSMEM>>>(Op, Wot, bo, out, MROWS, HID, HID);
}

// round 11
// speedup vs baseline: 1.0773x; 1.0773x over previous
#include <cuda_runtime.h>
#include <math.h>

#define HID     2048
#define KVD     512
#define HEADS   16
#define GROUPS  4
#define HDIM    128
#define BATCH   2
#define SEQ     2048
#define MROWS   (BATCH*SEQ)   // 4096

// ---------------- scratch (no cudaMalloc allowed) ----------------
__device__ float g_Q[(size_t)MROWS * HID];    // tf32, hdim cols pair-permuted
__device__ float g_K[(size_t)MROWS * KVD];    // tf32, hdim cols pair-permuted
__device__ float g_V[(size_t)MROWS * KVD];    // tf32, key rows pair-interleaved
__device__ float g_O[(size_t)MROWS * HID];    // tf32 plain
__device__ float g_Xt[(size_t)MROWS * HID];   // tf32 copy of X
__device__ float g_Wqt[(size_t)HID * HID];
__device__ float g_Wkt[(size_t)HID * KVD];
__device__ float g_Wvt[(size_t)HID * KVD];
__device__ float g_Wot[(size_t)HID * HID];

// ---------------- helpers ----------------
__device__ __forceinline__ unsigned f2tf(float x) {
    unsigned u;
    asm("cvt.rna.tf32.f32 %0, %1;" : "=r"(u) : "f"(x));
    return u;
}
__device__ __forceinline__ float tfs(float x) { return __uint_as_float(f2tf(x)); }
__device__ __forceinline__ unsigned uf(float x) { return __float_as_uint(x); }

// pair permutation within an 8-group: orig j -> stored position (j, j+4 adjacent)
__device__ __forceinline__ int pcol(int j) { return (j < 4) ? 2 * j : 2 * (j - 4) + 1; }

__device__ __forceinline__ void mma_tf32(float c[4], const unsigned a[4], const unsigned b[2]) {
    asm volatile(
        "mma.sync.aligned.m16n8k8.row.col.f32.tf32.tf32.f32 "
        "{%0,%1,%2,%3},{%4,%5,%6,%7},{%8,%9},{%0,%1,%2,%3};\n"
        : "+f"(c[0]), "+f"(c[1]), "+f"(c[2]), "+f"(c[3])
        : "r"(a[0]), "r"(a[1]), "r"(a[2]), "r"(a[3]), "r"(b[0]), "r"(b[1]));
}

__device__ __forceinline__ void cp_async16(void* smem, const void* gmem) {
    unsigned sa = (unsigned)__cvta_generic_to_shared(smem);
    asm volatile("cp.async.cg.shared.global [%0], [%1], 16;\n" :: "r"(sa), "l"(gmem));
}
#define CP_COMMIT asm volatile("cp.async.commit_group;\n")
#define CP_WAIT0  asm volatile("cp.async.wait_group 0;\n")

// ================= tf32 pre-cast: out[i] = tf32(in[i]) =================
__global__ __launch_bounds__(256) void tf32_cast(const float* __restrict__ in,
                                                 float* __restrict__ out, int n4)
{
    int i = blockIdx.x * 256 + threadIdx.x;
    if (i < n4) {
        float4 v = ((const float4*)in)[i];
        float4 o = make_float4(tfs(v.x), tfs(v.y), tfs(v.z), tfs(v.w));
        ((float4*)out)[i] = o;
    }
}

// ================= GEMM (tf32 tensor cores): C[M,N] = A[M,K]@W[K,N] + bias ===========
// R9 core. EPI: 0 = plain fp32 out; 1 = tf32 + N-col pair-permute (Q,K); 2 = tf32 + V row interleave
#define GBK 32
#define G_AS (128*36)
#define G_BS (32*136)
#define GSMEM ((2*G_AS + 2*G_BS) * 4)   // 71680 B

// shared device body (templated on EPI); bn passed explicitly for fused launches
template<int EPI>
__device__ __forceinline__ void gemm_body(
    const float* __restrict__ A, const float* __restrict__ W,
    const float* __restrict__ bias, float* __restrict__ C,
    int M, int N, int K, int bm, int bn, float* gsm)
{
    float (*As)[128][36]  = (float(*)[128][36])gsm;
    float (*Bs)[32][136]  = (float(*)[32][136])(gsm + 2 * G_AS);

    const int tid = threadIdx.x;
    const int lane = tid & 31, wid = tid >> 5;
    const int gid = lane >> 2, tig = lane & 3;
    const int wm = wid >> 1, wn = wid & 1;

    float acc[2][8][4];
#pragma unroll
    for (int i = 0; i < 2; i++)
#pragma unroll
        for (int j = 0; j < 8; j++)
#pragma unroll
            for (int v = 0; v < 4; v++) acc[i][j][v] = 0.f;

    const int T = K / GBK;

    auto load_stage = [&](int st, int t) {
        const int k0 = t * GBK;
#pragma unroll
        for (int u = 0; u < 4; u++) {
            int id = tid + u * 256;
            int ra = id >> 3, ca = id & 7;
            cp_async16(&As[st][ra][ca * 4],
                       A + (size_t)(bm + ra) * K + k0 + ca * 4);
            int rb = id >> 5, cb = id & 31;
            cp_async16(&Bs[st][rb][cb * 4],
                       W + (size_t)(k0 + rb) * N + bn + cb * 4);
        }
    };

    load_stage(0, 0);
    CP_COMMIT;

    for (int t = 0; t < T; t++) {
        const int st = t & 1;
        CP_WAIT0;
        __syncthreads();
        if (t + 1 < T) {
            load_stage(st ^ 1, t + 1);
            CP_COMMIT;
        }

#pragma unroll
        for (int kk = 0; kk < GBK; kk += 8) {
            unsigned a[2][4];
#pragma unroll
            for (int mt = 0; mt < 2; mt++) {
                int r = wm * 32 + mt * 16 + gid;
                a[mt][0] = uf(As[st][r][kk + tig]);
                a[mt][1] = uf(As[st][r + 8][kk + tig]);
                a[mt][2] = uf(As[st][r][kk + tig + 4]);
                a[mt][3] = uf(As[st][r + 8][kk + tig + 4]);
            }
#pragma unroll
            for (int nt = 0; nt < 8; nt++) {
                unsigned bf[2];
                int c = wn * 64 + nt * 8 + gid;
                bf[0] = uf(Bs[st][kk + tig][c]);
                bf[1] = uf(Bs[st][kk + tig + 4][c]);
                mma_tf32(acc[0][nt], a[0], bf);
                mma_tf32(acc[1][nt], a[1], bf);
            }
        }
    }

    // epilogue
    const int pj0 = pcol(2 * tig), pj1 = pcol(2 * tig + 1);
#pragma unroll
    for (int mt = 0; mt < 2; mt++) {
        int rbase = bm + wm * 32 + mt * 16 + gid;
#pragma unroll
        for (int nt = 0; nt < 8; nt++) {
            int cb = bn + wn * 64 + nt * 8;
            int c = cb + 2 * tig;
            float bx = bias[c], by = bias[c + 1];
            float v0 = acc[mt][nt][0] + bx, v1 = acc[mt][nt][1] + by;
            float v2 = acc[mt][nt][2] + bx, v3 = acc[mt][nt][3] + by;
            if (EPI == 0) {
                *(float2*)&C[(size_t)rbase * N + c] = make_float2(v0, v1);
                *(float2*)&C[(size_t)(rbase + 8) * N + c] = make_float2(v2, v3);
            } else if (EPI == 1) {
                C[(size_t)rbase * N + cb + pj0] = tfs(v0);
                C[(size_t)rbase * N + cb + pj1] = tfs(v1);
                C[(size_t)(rbase + 8) * N + cb + pj0] = tfs(v2);
                C[(size_t)(rbase + 8) * N + cb + pj1] = tfs(v3);
            } else {
                // V: row pair-interleave addr(r,c) = (r&~7)*N + (r&3)*2N + c*2 + ((r>>2)&1)
#pragma unroll
                for (int rr = 0; rr < 2; rr++) {
                    int r = rbase + rr * 8;
                    size_t base = (size_t)(r & ~7) * N + (size_t)(r & 3) * 2 * N + ((r >> 2) & 1);
                    float a0 = rr ? v2 : v0, a1 = rr ? v3 : v1;
                    C[base + (size_t)c * 2] = tfs(a0);
                    C[base + (size_t)(c + 1) * 2] = tfs(a1);
                }
            }
        }
    }
}

template<int EPI>
__global__ __launch_bounds__(256, 2) void gemm_mma(
    const float* __restrict__ A, const float* __restrict__ W,
    const float* __restrict__ bias, float* __restrict__ C,
    int M, int N, int K)
{
    extern __shared__ float gsm[];
    gemm_body<EPI>(A, W, bias, C, M, N, K,
                   blockIdx.y * 128, blockIdx.x * 128, gsm);
}

// fused K+V projection: grid.x = 8; bx<4 -> K (EPI1), else V (EPI2). One launch, 256 CTAs.
__global__ __launch_bounds__(256, 2) void gemm_mma_kv(
    const float* __restrict__ A,
    const float* __restrict__ Wk, const float* __restrict__ Wv,
    const float* __restrict__ bk, const float* __restrict__ bv,
    float* __restrict__ Ck, float* __restrict__ Cv,
    int M, int K)
{
    extern __shared__ float gsm[];
    const bool isK = blockIdx.x < 4;
    const int bn = (blockIdx.x & 3) * 128;
    const int bm = blockIdx.y * 128;
    if (isK)
        gemm_body<1>(A, Wk, bk, Ck, M, KVD, K, bm, bn, gsm);
    else
        gemm_body<2>(A, Wv, bv, Cv, M, KVD, K, bm, bn, gsm);
}

// ================= Flash attention on tensor cores =================
// 128 threads = 4 warps (warp owns 16 Q rows), Q tile 64x128, K/V tiles 32x128,
// double-buffered cp.async, 2 CTAs/SM. Conflict-free LDS.64 gathers (pads = 8 mod 32).
#define AQP 136
#define AKP 136
#define AVL 264
#define APP 40
#define OQ_  0
#define OKs  (64*AQP)                  // 8704
#define OVs  (OKs + 2*32*AKP)          // +8704
#define OPs  (OVs + 2*16*AVL)          // +8448
#define OMs  (OPs + 64*APP)            // +2560
#define ASMEM ((OMs + 2*32) * 4)       // 113920 B -> 2 CTAs/SM

__global__ __launch_bounds__(128, 2) void attn_mma(const int* __restrict__ mask)
{
    extern __shared__ float sm[];
    float (*Qs)[AQP]     = (float(*)[AQP])(sm + OQ_);
    float (*Ks)[32][AKP] = (float(*)[32][AKP])(sm + OKs);
    float (*Vs)[16][AVL] = (float(*)[16][AVL])(sm + OVs);
    float (*Ps)[APP]     = (float(*)[APP])(sm + OPs);
    int (*Ms)[32]        = (int(*)[32])(sm + OMs);

    const int tid = threadIdx.x;
    const int w = tid >> 5, lane = tid & 31;
    const int gid = lane >> 2, tig = lane & 3;
    const int qt = blockIdx.x, h = blockIdx.y, b = blockIdx.z;
    const int g = h % GROUPS;
    const int q0 = qt * 64;

    const float scale = 0.08838834764831845f;  // 1/sqrt(128)
    const float* Qg = g_Q + (size_t)(b * SEQ + q0) * HID + h * HDIM;
    const float* Kg0 = g_K + (size_t)(b * SEQ) * KVD + g * HDIM;
    const float* Vg0 = g_V + (size_t)(b * SEQ) * KVD;
    const int*   Mg0 = mask + b * SEQ;

    auto issue_kv = [&](int st, int kt) {
        const int k0 = kt * 32;
#pragma unroll
        for (int u = 0; u < 8; u++) {
            int id = tid + u * 128;
            int r = id >> 5, c4 = id & 31;
            cp_async16(&Ks[st][r][c4 * 4], Kg0 + (size_t)(k0 + r) * KVD + c4 * 4);
            int line = id >> 6, cc = id & 63;
            const float* src = Vg0 + (size_t)(k0 + (line >> 2) * 8) * KVD
                             + (size_t)(line & 3) * 2 * KVD + g * HDIM * 2 + cc * 4;
            cp_async16(&Vs[st][line][cc * 4], src);
        }
        if (tid < 8) cp_async16(&Ms[st][tid * 4], Mg0 + k0 + tid * 4);
    };

    issue_kv(0, 0);
    CP_COMMIT;

    // Q prologue: straight copy (already col-permuted + tf32), scale + re-round
#pragma unroll
    for (int u = 0; u < 16; u++) {
        int idx = tid + u * 128;
        int r = idx >> 5, c4 = idx & 31;
        float4 v = *(const float4*)(Qg + (size_t)r * HID + c4 * 4);
        float4 o = make_float4(tfs(v.x * scale), tfs(v.y * scale),
                               tfs(v.z * scale), tfs(v.w * scale));
        *(float4*)&Qs[r][c4 * 4] = o;
    }

    float m_run[2] = {-1e30f, -1e30f};
    float l_run[2] = {0.f, 0.f};
    float o_acc[16][4];
#pragma unroll
    for (int nt = 0; nt < 16; nt++)
#pragma unroll
        for (int v = 0; v < 4; v++) o_acc[nt][v] = 0.f;

    const int r = w * 16 + gid;
    const int pj0 = pcol(2 * tig), pj1 = pcol(2 * tig + 1);

    for (int kt = 0; kt < SEQ / 32; kt++) {
        const int st = kt & 1;
        CP_WAIT0;
        __syncthreads();
        if (kt + 1 < SEQ / 32) {
            issue_kv(st ^ 1, kt + 1);
            CP_COMMIT;
        }

        // ---- S = Q @ K^T (conflict-free LDS.64 gathers) ----
        float s[4][4];
#pragma unroll
        for (int nt = 0; nt < 4; nt++)
#pragma unroll
            for (int v = 0; v < 4; v++) s[nt][v] = 0.f;

#pragma unroll
        for (int ks = 0; ks < 16; ks++) {
            const int kk = ks * 8;
            float2 q0 = *(const float2*)&Qs[r][kk + 2 * tig];
            float2 q1 = *(const float2*)&Qs[r + 8][kk + 2 * tig];
            unsigned qa[4] = {uf(q0.x), uf(q1.x), uf(q0.y), uf(q1.y)};
#pragma unroll
            for (int nt = 0; nt < 4; nt++) {
                float2 kv = *(const float2*)&Ks[st][nt * 8 + gid][kk + 2 * tig];
                unsigned kb[2] = {uf(kv.x), uf(kv.y)};
                mma_tf32(s[nt], qa, kb);
            }
        }

        // ---- mask ----
#pragma unroll
        for (int nt = 0; nt < 4; nt++) {
            int c = nt * 8 + 2 * tig;
            if (Ms[st][c] == 0)     { s[nt][0] = -1e30f; s[nt][2] = -1e30f; }
            if (Ms[st][c + 1] == 0) { s[nt][1] = -1e30f; s[nt][3] = -1e30f; }
        }

        // ---- online softmax ----
#pragma unroll
        for (int hh = 0; hh < 2; hh++) {
            float mx = -1e30f;
#pragma unroll
            for (int nt = 0; nt < 4; nt++)
                mx = fmaxf(mx, fmaxf(s[nt][2 * hh], s[nt][2 * hh + 1]));
            mx = fmaxf(mx, __shfl_xor_sync(0xffffffffu, mx, 1));
            mx = fmaxf(mx, __shfl_xor_sync(0xffffffffu, mx, 2));
            float mnew = fmaxf(m_run[hh], mx);
            float corr = __expf(m_run[hh] - mnew);
            float sum = 0.f;
#pragma unroll
            for (int nt = 0; nt < 4; nt++) {
                float p0 = __expf(s[nt][2 * hh] - mnew);
                float p1 = __expf(s[nt][2 * hh + 1] - mnew);
                s[nt][2 * hh] = p0; s[nt][2 * hh + 1] = p1;
                sum += p0 + p1;
            }
            sum += __shfl_xor_sync(0xffffffffu, sum, 1);
            sum += __shfl_xor_sync(0xffffffffu, sum, 2);
            l_run[hh] = l_run[hh] * corr + sum;
            if (mnew > m_run[hh]) {
                m_run[hh] = mnew;
#pragma unroll
                for (int nt = 0; nt < 16; nt++) {
                    o_acc[nt][2 * hh] *= corr;
                    o_acc[nt][2 * hh + 1] *= corr;
                }
            }
        }

        // ---- store P (key-col pair permuted, matches V interleave) ----
#pragma unroll
        for (int nt = 0; nt < 4; nt++) {
            int cb = nt * 8;
            Ps[r][cb + pj0] = tfs(s[nt][0]);
            Ps[r][cb + pj1] = tfs(s[nt][1]);
            Ps[r + 8][cb + pj0] = tfs(s[nt][2]);
            Ps[r + 8][cb + pj1] = tfs(s[nt][3]);
        }
        __syncwarp();

        // ---- O += P @ V ----
#pragma unroll
        for (int ks = 0; ks < 4; ks++) {
            const int kk = ks * 8;
            float2 p0 = *(const float2*)&Ps[r][kk + 2 * tig];
            float2 p1 = *(const float2*)&Ps[r + 8][kk + 2 * tig];
            unsigned pa[4] = {uf(p0.x), uf(p1.x), uf(p0.y), uf(p1.y)};
            const int kp = kk / 2 + tig;
#pragma unroll
            for (int nt = 0; nt < 16; nt++) {
                float2 vv = *(const float2*)&Vs[st][kp][(nt * 8 + gid) * 2];
                unsigned vb[2] = {uf(vv.x), uf(vv.y)};
                mma_tf32(o_acc[nt], pa, vb);
            }
        }
    }

    // ---- epilogue: O /= l, tf32-rounded, plain layout ----
    float* Og = g_O + (size_t)(b * SEQ + q0) * HID + h * HDIM;
    const float i0 = 1.f / l_run[0], i1 = 1.f / l_run[1];
#pragma unroll
    for (int nt = 0; nt < 16; nt++) {
        int c = nt * 8 + 2 * tig;
        float2 v0 = make_float2(tfs(o_acc[nt][0] * i0), tfs(o_acc[nt][1] * i0));
        float2 v1 = make_float2(tfs(o_acc[nt][2] * i1), tfs(o_acc[nt][3] * i1));
        *(float2*)&Og[(size_t)r * HID + c] = v0;
        *(float2*)&Og[(size_t)(r + 8) * HID + c] = v1;
    }
}

// ================= launch =================
extern "C" void kernel_launch(void* const* d_in, const int* in_sizes, int n_in,
                              void* d_out, int out_size)
{
    const float* X    = (const float*)d_in[0];
    const int*   mask = (const int*)  d_in[1];
    const float* Wq   = (const float*)d_in[2];
    const float* bq   = (const float*)d_in[3];
    const float* Wk   = (const float*)d_in[4];
    const float* bk   = (const float*)d_in[5];
    const float* Wv   = (const float*)d_in[6];
    const float* bv   = (const float*)d_in[7];
    const float* Wo   = (const float*)d_in[8];
    const float* bo   = (const float*)d_in[9];
    float* out = (float*)d_out;

    float *Qp, *Kp, *Vp, *Op, *Xt, *Wqt, *Wkt, *Wvt, *Wot;
    cudaGetSymbolAddress((void**)&Qp, g_Q);
    cudaGetSymbolAddress((void**)&Kp, g_K);
    cudaGetSymbolAddress((void**)&Vp, g_V);
    cudaGetSymbolAddress((void**)&Op, g_O);
    cudaGetSymbolAddress((void**)&Xt, g_Xt);
    cudaGetSymbolAddress((void**)&Wqt, g_Wqt);
    cudaGetSymbolAddress((void**)&Wkt, g_Wkt);
    cudaGetSymbolAddress((void**)&Wvt, g_Wvt);
    cudaGetSymbolAddress((void**)&Wot, g_Wot);

    cudaFuncSetAttribute(gemm_mma<0>, cudaFuncAttributeMaxDynamicSharedMemorySize, GSMEM);
    cudaFuncSetAttribute(gemm_mma<1>, cudaFuncAttributeMaxDynamicSharedMemorySize, GSMEM);
    cudaFuncSetAttribute(gemm_mma_kv, cudaFuncAttributeMaxDynamicSharedMemorySize, GSMEM);
    cudaFuncSetAttribute(attn_mma, cudaFuncAttributeMaxDynamicSharedMemorySize, ASMEM);

    // pre-round inputs to tf32
    {
        int nX  = MROWS * HID / 4, nWq = HID * HID / 4,
            nWk = HID * KVD / 4,  nWo = HID * HID / 4;
        tf32_cast<<<(nX  + 255) / 256, 256>>>(X,  Xt,  nX);
        tf32_cast<<<(nWq + 255) / 256, 256>>>(Wq, Wqt, nWq);
        tf32_cast<<<(nWk + 255) / 256, 256>>>(Wk, Wkt, nWk);
        tf32_cast<<<(nWk + 255) / 256, 256>>>(Wv, Wvt, nWk);
        tf32_cast<<<(nWo + 255) / 256, 256>>>(Wo, Wot, nWo);
    }

    dim3 blk(256);
    gemm_mma<1><<<dim3(HID / 128, MROWS / 128), blk, GSMEM>>>(Xt, Wqt, bq, Qp, MROWS, HID, HID);
    gemm_mma_kv<<<dim3(8, MROWS / 128), blk, GSMEM>>>(Xt, Wkt, Wvt, bk, bv, Kp, Vp, MROWS, HID);

    attn_mma<<<dim3(SEQ / 64, HEADS, BATCH), dim3(128), ASMEM>>>(mask);

    gemm_mma<0><<<dim3(HID / 128, MROWS / 128), blk, GSMEM>>>(Op, Wot, bo, out, MROWS, HID, HID);
}